// round 6
// baseline (speedup 1.0000x reference)
#include <cuda_runtime.h>
#include <cuda_fp16.h>
#include <cstdint>

// ImageWarped: trilinear sampling of [B,128,128,128,1] fp32 at [B,N,3] coords.
// B=2, N=2097152.
//
// R6 structure: overlap pack and sample across batches.
//   K1: pack batch0          (8192 blocks)
//   K2: pack batch1 (first)  + sample batch0  in ONE grid (independent work)
//   K3: sample batch1
// Pack: 2x2x2 fp16 corner cube per voxel in one uint4 (64 MB scratch).
// Sample: ONE scattered LDG.128 per sample, 2 samples/thread, evict-first
// streaming (__ldcs/__stcs) for grid/out.
//
// fp16 quantization -> rel_err ~2.1e-4 (verified R3-R5, < 1e-3 gate).
// Boundary-clamped "+1" entries are weight-masked (exactly-zero fractional
// weights per the reference floor/ceil convention).

#define BATCH 2
#define NPTS  2097152
#define HVOX  (128 * 128 * 128)            // 2097152 voxels per batch
#define VOXELS (BATCH * HVOX)
#define CLAMP_LO 0.001f
#define CLAMP_HI 126.999f

#define PACK_BLOCKS   (HVOX / 256)         // 8192
#define SAMPLE_BLOCKS (NPTS / 2 / 256)     // 4096 (2 samples/thread)

__device__ uint4 g_packed[VOXELS];         // 64 MB scratch

__device__ __forceinline__ uint32_t pack_h2(float a, float b) {
    __half2 h = __floats2half2_rn(a, b);
    return *reinterpret_cast<uint32_t*>(&h);
}

__device__ __forceinline__ void pack_voxel(const float* __restrict__ image, int idx)
{
    const int z = idx & 127;
    const int y = (idx >> 7) & 127;
    const int x = (idx >> 14) & 127;
    const int dz = (z < 127) ? 1 : 0;
    const int dy = (y < 127) ? 128 : 0;
    const int dx = (x < 127) ? 16384 : 0;

    const float c111 = __ldg(image + idx);
    const float c112 = __ldg(image + idx + dz);
    const float c121 = __ldg(image + idx + dy);
    const float c122 = __ldg(image + idx + dy + dz);
    const float c211 = __ldg(image + idx + dx);
    const float c212 = __ldg(image + idx + dx + dz);
    const float c221 = __ldg(image + idx + dx + dy);
    const float c222 = __ldg(image + idx + dx + dy + dz);

    uint4 p;
    p.x = pack_h2(c111, c112);
    p.y = pack_h2(c121, c122);
    p.z = pack_h2(c211, c212);
    p.w = pack_h2(c221, c222);
    g_packed[idx] = p;
}

__device__ __forceinline__ float sample_one(float gx, float gy, float gz, int base_b)
{
    const float x = fminf(fmaxf(gx * 128.0f, CLAMP_LO), CLAMP_HI);
    const float y = fminf(fmaxf(gy * 128.0f, CLAMP_LO), CLAMP_HI);
    const float z = fminf(fmaxf(gz * 128.0f, CLAMP_LO), CLAMP_HI);

    const float x1f = floorf(x), x2f = ceilf(x);
    const float y1f = floorf(y), y2f = ceilf(y);
    const float z1f = floorf(z), z2f = ceilf(z);

    const int cube = base_b + (((int)x1f) << 14) + (((int)y1f) << 7) + (int)z1f;
    const uint4 p = __ldg(&g_packed[cube]);   // one 128-bit scattered gather

    const float2 a1 = __half22float2(*reinterpret_cast<const __half2*>(&p.x)); // c111,c112
    const float2 a2 = __half22float2(*reinterpret_cast<const __half2*>(&p.y)); // c121,c122
    const float2 b1 = __half22float2(*reinterpret_cast<const __half2*>(&p.z)); // c211,c212
    const float2 b2 = __half22float2(*reinterpret_cast<const __half2*>(&p.w)); // c221,c222

    const float wx = x - x1f, wx2 = x2f - x;
    const float wy = y - y1f, wy2 = y2f - y;
    const float wz = z - z1f, wz2 = z2f - z;

    const float lerp_y1 = (b1.x * wx + a1.x * wx2) * wy2
                        + (b2.x * wx + a2.x * wx2) * wy;
    const float lerp_y2 = (b1.y * wx + a1.y * wx2) * wy2
                        + (b2.y * wx + a2.y * wx2) * wy;
    return lerp_y2 * wz + lerp_y1 * wz2;
}

// Sample pair: thread t' handles samples (sample_base + 2*t'), (.. + 1).
__device__ __forceinline__ void sample_pair(const float* __restrict__ grid,
                                            float* __restrict__ out,
                                            int tprime, int sample_base, int base_b)
{
    const int s = sample_base + (tprime << 1);
    const float2* g = (const float2*)(grid + 3 * (size_t)s);
    const float2 q0 = __ldcs(g + 0);   // x0 y0
    const float2 q1 = __ldcs(g + 1);   // z0 x1
    const float2 q2 = __ldcs(g + 2);   // y1 z1

    float2 r;
    r.x = sample_one(q0.x, q0.y, q1.x, base_b);
    r.y = sample_one(q1.y, q2.x, q2.y, base_b);
    __stcs((float2*)(out + s), r);
}

__global__ void __launch_bounds__(256)
pack0_kernel(const float* __restrict__ image)
{
    pack_voxel(image, blockIdx.x * 256 + threadIdx.x);         // batch 0 voxels
}

// Fused: pack batch1 (blocks [0, PACK_BLOCKS)) + sample batch0 (rest).
__global__ void __launch_bounds__(256)
mid_kernel(const float* __restrict__ image,
           const float* __restrict__ grid,
           float* __restrict__ out)
{
    if (blockIdx.x < PACK_BLOCKS) {
        pack_voxel(image, HVOX + blockIdx.x * 256 + threadIdx.x);  // batch 1
    } else {
        const int tprime = (blockIdx.x - PACK_BLOCKS) * 256 + threadIdx.x;
        sample_pair(grid, out, tprime, 0, 0);                      // batch 0
    }
}

__global__ void __launch_bounds__(256)
sample1_kernel(const float* __restrict__ grid,
               float* __restrict__ out)
{
    const int tprime = blockIdx.x * 256 + threadIdx.x;
    sample_pair(grid, out, tprime, NPTS, HVOX);                    // batch 1
}

extern "C" void kernel_launch(void* const* d_in, const int* in_sizes, int n_in,
                              void* d_out, int out_size)
{
    const float* image = (const float*)d_in[0];
    const float* grid  = (const float*)d_in[1];
    float* out = (float*)d_out;

    pack0_kernel<<<PACK_BLOCKS, 256>>>(image);
    mid_kernel<<<PACK_BLOCKS + SAMPLE_BLOCKS, 256>>>(image, grid, out);
    sample1_kernel<<<SAMPLE_BLOCKS, 256>>>(grid, out);
}

// round 7
// speedup vs baseline: 1.0761x; 1.0761x over previous
#include <cuda_runtime.h>
#include <cuda_fp16.h>
#include <cstdint>

// ImageWarped: trilinear sampling of [B,128,128,128,1] fp32 at [B,N,3] coords.
// B=2, N=2097152.
//
// Phase 1 (pack): per voxel, the 2x2x2 fp16 corner cube in one uint4
//   (64 MB scratch). Vectorized 2 z-voxels/thread: 4x LDG.64 + 4 edge
//   scalars per pair (halves LSU issue count vs scalar pack).
// Phase 2 (sample): ONE scattered LDG.128 per sample, 2 samples/thread,
//   evict-first streaming for grid/out. At the L1tex wavefront-replay
//   floor (~30.5us) — unchanged from R5.
//
// fp16 quantization -> rel_err ~2.1e-4 (< 1e-3 gate, verified R3-R6).
// All out-of-range "+1" neighbors are weight-masked (exactly-zero
// fractional weights per the reference floor/ceil convention).

#define BATCH 2
#define NPTS  2097152
#define VOXELS (BATCH * 128 * 128 * 128)   // 4194304
#define CLAMP_LO 0.001f
#define CLAMP_HI 126.999f

__device__ uint4 g_packed[VOXELS];         // 64 MB scratch

__device__ __forceinline__ uint32_t pack_h2(float a, float b) {
    __half2 h = __floats2half2_rn(a, b);
    return *reinterpret_cast<uint32_t*>(&h);
}

// One thread packs voxels (idx, idx+1) — a z-pair (idx even).
__global__ void __launch_bounds__(256)
pack_kernel(const float* __restrict__ image)
{
    const int t = blockIdx.x * blockDim.x + threadIdx.x;     // pair id
    const int idx = t << 1;                                  // even voxel
    const int z = idx & 127;                                 // 0,2,...,126
    const int y = (idx >> 7) & 127;
    const int x = (idx >> 14) & 127;
    const int dy = (y < 127) ? 128 : 0;                      // weight-masked at 127
    const int dx = (x < 127) ? 16384 : 0;

    const int i00 = idx;                 // (x,   y  )
    const int i01 = idx + dy;            // (x,   y+1)
    const int i10 = idx + dx;            // (x+1, y  )
    const int i11 = idx + dx + dy;       // (x+1, y+1)

    const float2 r00 = __ldg((const float2*)(image + i00));  // z, z+1
    const float2 r01 = __ldg((const float2*)(image + i01));
    const float2 r10 = __ldg((const float2*)(image + i10));
    const float2 r11 = __ldg((const float2*)(image + i11));

    // z+2 edge value; at z==126 voxel z=127's +1 neighbor is weight-masked.
    const bool he = (z < 126);
    const float e00 = he ? __ldg(image + i00 + 2) : r00.y;
    const float e01 = he ? __ldg(image + i01 + 2) : r01.y;
    const float e10 = he ? __ldg(image + i10 + 2) : r10.y;
    const float e11 = he ? __ldg(image + i11 + 2) : r11.y;

    uint4 p0, p1;
    p0.x = pack_h2(r00.x, r00.y);   // voxel z:   c111,c112
    p0.y = pack_h2(r01.x, r01.y);   //            c121,c122
    p0.z = pack_h2(r10.x, r10.y);   //            c211,c212
    p0.w = pack_h2(r11.x, r11.y);   //            c221,c222
    p1.x = pack_h2(r00.y, e00);     // voxel z+1
    p1.y = pack_h2(r01.y, e01);
    p1.z = pack_h2(r10.y, e10);
    p1.w = pack_h2(r11.y, e11);

    g_packed[idx]     = p0;
    g_packed[idx + 1] = p1;
}

__device__ __forceinline__ float sample_one(float gx, float gy, float gz, int base_b)
{
    const float x = fminf(fmaxf(gx * 128.0f, CLAMP_LO), CLAMP_HI);
    const float y = fminf(fmaxf(gy * 128.0f, CLAMP_LO), CLAMP_HI);
    const float z = fminf(fmaxf(gz * 128.0f, CLAMP_LO), CLAMP_HI);

    const float x1f = floorf(x), x2f = ceilf(x);
    const float y1f = floorf(y), y2f = ceilf(y);
    const float z1f = floorf(z), z2f = ceilf(z);

    const int cube = base_b + (((int)x1f) << 14) + (((int)y1f) << 7) + (int)z1f;
    const uint4 p = __ldg(&g_packed[cube]);   // one 128-bit scattered gather

    const float2 a1 = __half22float2(*reinterpret_cast<const __half2*>(&p.x)); // c111,c112
    const float2 a2 = __half22float2(*reinterpret_cast<const __half2*>(&p.y)); // c121,c122
    const float2 b1 = __half22float2(*reinterpret_cast<const __half2*>(&p.z)); // c211,c212
    const float2 b2 = __half22float2(*reinterpret_cast<const __half2*>(&p.w)); // c221,c222

    const float wx = x - x1f, wx2 = x2f - x;
    const float wy = y - y1f, wy2 = y2f - y;
    const float wz = z - z1f, wz2 = z2f - z;

    const float lerp_y1 = (b1.x * wx + a1.x * wx2) * wy2
                        + (b2.x * wx + a2.x * wx2) * wy;
    const float lerp_y2 = (b1.y * wx + a1.y * wx2) * wy2
                        + (b2.y * wx + a2.y * wx2) * wy;
    return lerp_y2 * wz + lerp_y1 * wz2;
}

__global__ void __launch_bounds__(256)
trilinear_kernel(const float* __restrict__ grid,
                 float* __restrict__ out)
{
    const int t = blockIdx.x * blockDim.x + threadIdx.x;     // 2 samples per thread
    const int s = t << 1;
    const int base_b = (s >> 21) << 21;                      // batch base

    const float2* g = (const float2*)(grid + 3 * (size_t)s);
    const float2 q0 = __ldcs(g + 0);   // x0 y0
    const float2 q1 = __ldcs(g + 1);   // z0 x1
    const float2 q2 = __ldcs(g + 2);   // y1 z1

    float2 r;
    r.x = sample_one(q0.x, q0.y, q1.x, base_b);
    r.y = sample_one(q1.y, q2.x, q2.y, base_b);

    __stcs((float2*)(out + s), r);
}

extern "C" void kernel_launch(void* const* d_in, const int* in_sizes, int n_in,
                              void* d_out, int out_size)
{
    const float* image = (const float*)d_in[0];
    const float* grid  = (const float*)d_in[1];
    float* out = (float*)d_out;

    pack_kernel<<<(VOXELS / 2) / 256, 256>>>(image);
    trilinear_kernel<<<(BATCH * NPTS / 2) / 256, 256>>>(grid, out);
}

// round 9
// speedup vs baseline: 1.1338x; 1.0537x over previous
#include <cuda_runtime.h>
#include <cuda_fp16.h>
#include <cstdint>

// ImageWarped: trilinear sampling of [B,128,128,128,1] fp32 at [B,N,3] coords.
// B=2, N=2097152.
//
// Phase 1 (pack): per voxel, 2x2x2 fp16 corner cube in one uint4 (64 MB
//   scratch), stored with an L2::evict_last cache policy (createpolicy +
//   st.global.L2::cache_hint) so the scratch stays L2-resident.
// Phase 2 (sample): ONE scattered 16B gather per sample with the same
//   evict-last policy; grid/out use evict-first streaming (__ldcs/__stcs).
//
// Policy split: 64 MB evict-last scratch vs 64 MB/launch evict-first stream
// in a 126 MB L2 -> gathers become L2 hits; dirty scratch lines get
// overwritten before eviction (no steady-state writebacks).
//
// fp16 quantization -> rel_err ~2.1e-4 (< 1e-3 gate, verified R3-R7).
// Out-of-range "+1" neighbors are weight-masked (exactly-zero fractional
// weights per the reference floor/ceil convention).

#define BATCH 2
#define NPTS  2097152
#define VOXELS (BATCH * 128 * 128 * 128)   // 4194304
#define CLAMP_LO 0.001f
#define CLAMP_HI 126.999f

__device__ uint4 g_packed[VOXELS];         // 64 MB scratch

__device__ __forceinline__ uint32_t pack_h2(float a, float b) {
    __half2 h = __floats2half2_rn(a, b);
    return *reinterpret_cast<uint32_t*>(&h);
}

__device__ __forceinline__ uint64_t mk_evict_last_policy() {
    uint64_t pol;
    asm("createpolicy.fractional.L2::evict_last.b64 %0, 1.0;" : "=l"(pol));
    return pol;
}

__device__ __forceinline__ void st_hint_v4(uint4* p, uint4 v, uint64_t pol) {
    asm volatile("st.global.L2::cache_hint.v4.b32 [%0], {%1,%2,%3,%4}, %5;"
                 :: "l"(p), "r"(v.x), "r"(v.y), "r"(v.z), "r"(v.w), "l"(pol)
                 : "memory");
}

__device__ __forceinline__ uint4 ld_nc_hint_v4(const uint4* p, uint64_t pol) {
    uint4 v;
    asm volatile("ld.global.nc.L2::cache_hint.v4.b32 {%0,%1,%2,%3}, [%4], %5;"
                 : "=r"(v.x), "=r"(v.y), "=r"(v.z), "=r"(v.w)
                 : "l"(p), "l"(pol));
    return v;
}

__global__ void __launch_bounds__(256)
pack_kernel(const float* __restrict__ image)
{
    const uint64_t pol = mk_evict_last_policy();
    const int idx = blockIdx.x * blockDim.x + threadIdx.x;   // (b,x,y,z) linear
    const int z = idx & 127;
    const int y = (idx >> 7) & 127;
    const int x = (idx >> 14) & 127;
    const int dz = (z < 127) ? 1 : 0;
    const int dy = (y < 127) ? 128 : 0;
    const int dx = (x < 127) ? 16384 : 0;

    const float c111 = __ldg(image + idx);
    const float c112 = __ldg(image + idx + dz);
    const float c121 = __ldg(image + idx + dy);
    const float c122 = __ldg(image + idx + dy + dz);
    const float c211 = __ldg(image + idx + dx);
    const float c212 = __ldg(image + idx + dx + dz);
    const float c221 = __ldg(image + idx + dx + dy);
    const float c222 = __ldg(image + idx + dx + dy + dz);

    uint4 p;
    p.x = pack_h2(c111, c112);
    p.y = pack_h2(c121, c122);
    p.z = pack_h2(c211, c212);
    p.w = pack_h2(c221, c222);
    st_hint_v4(&g_packed[idx], p, pol);      // evict-last: pin scratch in L2
}

__device__ __forceinline__ float sample_one(float gx, float gy, float gz,
                                            int base_b, uint64_t pol)
{
    const float x = fminf(fmaxf(gx * 128.0f, CLAMP_LO), CLAMP_HI);
    const float y = fminf(fmaxf(gy * 128.0f, CLAMP_LO), CLAMP_HI);
    const float z = fminf(fmaxf(gz * 128.0f, CLAMP_LO), CLAMP_HI);

    const float x1f = floorf(x), x2f = ceilf(x);
    const float y1f = floorf(y), y2f = ceilf(y);
    const float z1f = floorf(z), z2f = ceilf(z);

    const int cube = base_b + (((int)x1f) << 14) + (((int)y1f) << 7) + (int)z1f;
    const uint4 p = ld_nc_hint_v4(&g_packed[cube], pol);   // 16B scattered gather

    const float2 a1 = __half22float2(*reinterpret_cast<const __half2*>(&p.x)); // c111,c112
    const float2 a2 = __half22float2(*reinterpret_cast<const __half2*>(&p.y)); // c121,c122
    const float2 b1 = __half22float2(*reinterpret_cast<const __half2*>(&p.z)); // c211,c212
    const float2 b2 = __half22float2(*reinterpret_cast<const __half2*>(&p.w)); // c221,c222

    const float wx = x - x1f, wx2 = x2f - x;
    const float wy = y - y1f, wy2 = y2f - y;
    const float wz = z - z1f, wz2 = z2f - z;

    const float lerp_y1 = (b1.x * wx + a1.x * wx2) * wy2
                        + (b2.x * wx + a2.x * wx2) * wy;
    const float lerp_y2 = (b1.y * wx + a1.y * wx2) * wy2
                        + (b2.y * wx + a2.y * wx2) * wy;
    return lerp_y2 * wz + lerp_y1 * wz2;
}

__global__ void __launch_bounds__(256)
trilinear_kernel(const float* __restrict__ grid,
                 float* __restrict__ out)
{
    const uint64_t pol = mk_evict_last_policy();
    const int t = blockIdx.x * blockDim.x + threadIdx.x;     // 2 samples per thread
    const int s = t << 1;
    const int base_b = (s >> 21) << 21;                      // batch base

    const float2* g = (const float2*)(grid + 3 * (size_t)s);
    const float2 q0 = __ldcs(g + 0);   // x0 y0
    const float2 q1 = __ldcs(g + 1);   // z0 x1
    const float2 q2 = __ldcs(g + 2);   // y1 z1

    float2 r;
    r.x = sample_one(q0.x, q0.y, q1.x, base_b, pol);
    r.y = sample_one(q1.y, q2.x, q2.y, base_b, pol);

    __stcs((float2*)(out + s), r);     // evict-first streaming store
}

extern "C" void kernel_launch(void* const* d_in, const int* in_sizes, int n_in,
                              void* d_out, int out_size)
{
    const float* image = (const float*)d_in[0];
    const float* grid  = (const float*)d_in[1];
    float* out = (float*)d_out;

    pack_kernel<<<VOXELS / 256, 256>>>(image);
    trilinear_kernel<<<(BATCH * NPTS / 2) / 256, 256>>>(grid, out);
}